// round 13
// baseline (speedup 1.0000x reference)
#include <cuda_runtime.h>
#include <cuda_bf16.h>
#include <cstdint>

// ExpertCapacityBuffer: N tokens, TOP_K=2, 64 experts.
// capacity = ceil(1.25*N*2/64). Flat slot-major: f = slot*N + tok.
// rank(f) = #{g<f : expert(g)==expert(f)}; keep iff rank < capacity.
//
// Overflow shortcut: expert e drops anything iff total(e) > capacity.
// Fused kernel (nbt <= 132, co-resident): phase 1 histograms + g_tot atomics;
// one counter barrier; phase 2 = register-resident copy (fast) or exact ranks
// reusing the phase-1 match results (slow, cold path).
// Fallback (big inputs): R12 two-kernel pipeline.

#define NE   64
#define NEP  65              // padded row kills smem bank conflicts
#define TPB  1024
#define EPT  1024
#define MAXROWS 4096
#define FUSE_MAX_BLOCKS 132

__device__ int g_cnt[MAXROWS][NE];
__device__ int g_tot[NE];    // zero at start; reset by last block
__device__ int g_done  = 0;
__device__ int g_done2 = 0;

__device__ __forceinline__ int ld_acq(const int* p) {
    int v;
    asm volatile("ld.acquire.gpu.b32 %0, [%1];" : "=r"(v) : "l"(p) : "memory");
    return v;
}

// warp-0 dtype probe: int64 values <64 => odd 32-bit words of first 256B zero.
__device__ __forceinline__ void probe_w0(const void* eraw, int lane, int* s_is64) {
    if (threadIdx.x < 32) {
        unsigned x = ((const unsigned*)eraw)[2 * lane + 1];
        unsigned nz = __ballot_sync(0xFFFFFFFFu, x != 0u);
        if (lane == 0) *s_is64 = (nz == 0u);
    }
}
__device__ __forceinline__ bool probe_warp(const void* eraw) {
    unsigned x = ((const unsigned*)eraw)[2 * (threadIdx.x & 31) + 1];
    return __ballot_sync(0xFFFFFFFFu, x != 0u) == 0u;
}

// ================== FUSED kernel (co-resident grids) ==================
__global__ void __launch_bounds__(TPB, 1)
k_fused(const float* __restrict__ w, const void* __restrict__ eraw,
        int n_tok, int capacity, int nbt,
        float* __restrict__ out_w, void* __restrict__ out_idx, int idx_mode,
        float* __restrict__ out_mask) {
    __shared__ int hA[32][NEP];
    __shared__ int hB[32][NEP];
    __shared__ int partA[16][NE];
    __shared__ int partB[16][NE];
    __shared__ int offA[NE], offB[NE];
    __shared__ int s_is64;
    const int t = threadIdx.x, b = blockIdx.x;
    const int warp = t >> 5, lane = t & 31;
    const unsigned lt = (1u << lane) - 1u;

    const int tok = b * EPT + t;
    const bool valid = tok < n_tok;

    // ---- phase 1: eager loads + histogram ----
    int2 v32 = make_int2(0, 0);
    float2 wv = make_float2(0.f, 0.f);
    if (valid) {
        v32 = __ldg((const int2*)eraw + tok);
        wv  = __ldg((const float2*)w + tok);
    }
    ((int*)hA)[t] = 0; ((int*)hA)[t + TPB] = 0;
    ((int*)hB)[t] = 0; ((int*)hB)[t + TPB] = 0;
    if (t < 32 * NEP - 2 * TPB) { ((int*)hA)[t + 2 * TPB] = 0; ((int*)hB)[t + 2 * TPB] = 0; }
    probe_w0(eraw, lane, &s_is64);
    __syncthreads();

    int e0 = NE + lane, e1 = NE + lane;      // unique keys for invalid lanes
    if (valid) {
        if (s_is64) {
            longlong2 v = __ldg((const longlong2*)eraw + tok);
            e0 = (int)v.x & (NE - 1); e1 = (int)v.y & (NE - 1);
        } else {
            e0 = v32.x & (NE - 1); e1 = v32.y & (NE - 1);
        }
    }
    unsigned m0 = __match_any_sync(0xFFFFFFFFu, e0);
    unsigned m1 = __match_any_sync(0xFFFFFFFFu, e1);
    const int wr0 = __popc(m0 & lt), wr1 = __popc(m1 & lt);
    if (valid && wr0 == 0) hA[warp][e0] = __popc(m0);
    if (valid && wr1 == 0) hB[warp][e1] = __popc(m1);
    __syncthreads();

    if (t < NE) {
        int s = 0;
        #pragma unroll
        for (int ww = 0; ww < 32; ww++) s += hA[ww][t];
        g_cnt[b][t] = s;
        if (s) atomicAdd(&g_tot[t], s);
    } else if (t < 2 * NE) {
        const int e = t - NE;
        int s = 0;
        #pragma unroll
        for (int ww = 0; ww < 32; ww++) s += hB[ww][e];
        g_cnt[nbt + b][e] = s;
        if (s) atomicAdd(&g_tot[e], s);
    }
    __syncthreads();

    // ---- single counter barrier ----
    if (t == 0) {
        __threadfence();
        atomicAdd(&g_done, 1);
        while (ld_acq(&g_done) < nbt) { }
    }
    __syncthreads();

    // ---- phase 2 ----
    const int ta = g_tot[lane], tb = g_tot[lane + 32];
    const bool overflow =
        __ballot_sync(0xFFFFFFFFu, (ta > capacity) || (tb > capacity)) != 0u;

    if (!overflow) {
        // fast path: everything kept; all operands already in registers
        if (valid) {
            ((float2*)out_w)[tok] = wv;
            if (idx_mode == 1) {
                ((float2*)out_idx)[tok] = make_float2((float)e0, (float)e1);
            } else if (idx_mode == 2) {
                longlong2 iv; iv.x = e0; iv.y = e1;
                ((longlong2*)out_idx)[tok] = iv;
            }
            if (out_mask) out_mask[tok] = ((wv.x + wv.y) == 0.0f) ? 1.0f : 0.0f;
        }
    } else {
        // slow path: exact ranks; warp hists (hA/hB) and match regs still live
        {
            const int e = t & (NE - 1), c = t >> 6;
            const int limA = b, limB = nbt + b;
            int accA = 0, accB = 0;
            for (int r = c; r < limB; r += 16) {
                int v = g_cnt[r][e];
                accB += v;
                if (r < limA) accA += v;
            }
            partA[c][e] = accA;
            partB[c][e] = accB;
        }
        __syncthreads();

        #pragma unroll
        for (int k = 0; k < 4; k++) {
            const int p = warp * 4 + k;
            const int e = p & (NE - 1);
            const bool isB = p >= NE;
            int v = isB ? hB[lane][e] : hA[lane][e];
            int x = v;
            #pragma unroll
            for (int d = 1; d < 32; d <<= 1) {
                int y = __shfl_up_sync(0xFFFFFFFFu, x, d);
                if (lane >= d) x += y;
            }
            if (isB) hB[lane][e] = x - v; else hA[lane][e] = x - v;
            int pv = (lane < 16) ? (isB ? partB[lane][e] : partA[lane][e]) : 0;
            #pragma unroll
            for (int d = 8; d > 0; d >>= 1) pv += __shfl_xor_sync(0xFFFFFFFFu, pv, d);
            if (lane == 0) { if (isB) offB[e] = pv; else offA[e] = pv; }
        }
        __syncthreads();

        if (valid) {
            const int rank0 = offA[e0] + hA[warp][e0] + wr0;
            const int rank1 = offB[e1] + hB[warp][e1] + wr1;
            const float w0 = (rank0 < capacity) ? wv.x : 0.0f;
            const float w1 = (rank1 < capacity) ? wv.y : 0.0f;
            ((float2*)out_w)[tok] = make_float2(w0, w1);
            if (idx_mode == 1) {
                ((float2*)out_idx)[tok] = make_float2((float)e0, (float)e1);
            } else if (idx_mode == 2) {
                longlong2 iv; iv.x = e0; iv.y = e1;
                ((longlong2*)out_idx)[tok] = iv;
            }
            if (out_mask) out_mask[tok] = ((w0 + w1) == 0.0f) ? 1.0f : 0.0f;
        }
    }

    // ---- reset for next graph replay (last block; all reads done) ----
    __syncthreads();
    if (t == 0) {
        if (atomicAdd(&g_done2, 1) == nbt - 1) {
            #pragma unroll
            for (int e = 0; e < NE; e++) g_tot[e] = 0;
            g_done = 0; g_done2 = 0;
        }
    }
}

// ================== Fallback two-kernel pipeline (large inputs) ==================
__global__ void __launch_bounds__(TPB)
k_count(const void* __restrict__ eraw, int n_tok, int nbt) {
    __shared__ int hA[32][NEP];
    __shared__ int hB[32][NEP];
    __shared__ int s_is64;
    const int t = threadIdx.x, b = blockIdx.x;
    const int warp = t >> 5, lane = t & 31;
    const unsigned lt = (1u << lane) - 1u;
    const int tok = b * EPT + t;
    const bool valid = tok < n_tok;

    int2 v32 = make_int2(0, 0);
    if (valid) v32 = __ldg((const int2*)eraw + tok);
    ((int*)hA)[t] = 0; ((int*)hA)[t + TPB] = 0;
    ((int*)hB)[t] = 0; ((int*)hB)[t + TPB] = 0;
    if (t < 32 * NEP - 2 * TPB) { ((int*)hA)[t + 2 * TPB] = 0; ((int*)hB)[t + 2 * TPB] = 0; }
    probe_w0(eraw, lane, &s_is64);
    __syncthreads();

    int e0 = NE + lane, e1 = NE + lane;
    if (valid) {
        if (s_is64) {
            longlong2 v = __ldg((const longlong2*)eraw + tok);
            e0 = (int)v.x & (NE - 1); e1 = (int)v.y & (NE - 1);
        } else {
            e0 = v32.x & (NE - 1); e1 = v32.y & (NE - 1);
        }
    }
    unsigned m0 = __match_any_sync(0xFFFFFFFFu, e0);
    unsigned m1 = __match_any_sync(0xFFFFFFFFu, e1);
    if (valid && !(m0 & lt)) hA[warp][e0] = __popc(m0);
    if (valid && !(m1 & lt)) hB[warp][e1] = __popc(m1);
    __syncthreads();

    if (t < NE) {
        int s = 0;
        #pragma unroll
        for (int ww = 0; ww < 32; ww++) s += hA[ww][t];
        g_cnt[b][t] = s;
        if (s) atomicAdd(&g_tot[t], s);
    } else if (t < 2 * NE) {
        const int e = t - NE;
        int s = 0;
        #pragma unroll
        for (int ww = 0; ww < 32; ww++) s += hB[ww][e];
        g_cnt[nbt + b][e] = s;
        if (s) atomicAdd(&g_tot[e], s);
    }
}

__global__ void __launch_bounds__(TPB)
k_apply(const float* __restrict__ w, const void* __restrict__ eraw,
        int n_tok, int capacity, int nbt,
        float* __restrict__ out_w, void* __restrict__ out_idx, int idx_mode,
        float* __restrict__ out_mask) {
    __shared__ int hA[32][NEP];
    __shared__ int hB[32][NEP];
    __shared__ int partA[16][NE];
    __shared__ int partB[16][NE];
    __shared__ int offA[NE], offB[NE];
    const int t = threadIdx.x, b = blockIdx.x;
    const int warp = t >> 5, lane = t & 31;
    const unsigned lt = (1u << lane) - 1u;
    const int tok = b * EPT + t;
    const bool valid = tok < n_tok;

    int2 v32 = make_int2(0, 0);
    float2 wv = make_float2(0.f, 0.f);
    if (valid) {
        v32 = __ldg((const int2*)eraw + tok);
        wv  = __ldg((const float2*)w + tok);
    }
    const bool is64 = probe_warp(eraw);
    const int ta = g_tot[lane], tb = g_tot[lane + 32];
    const bool overflow =
        __ballot_sync(0xFFFFFFFFu, (ta > capacity) || (tb > capacity)) != 0u;

    int e0 = NE + lane, e1 = NE + lane;
    if (valid && (overflow || idx_mode)) {
        if (is64) {
            longlong2 v = __ldg((const longlong2*)eraw + tok);
            e0 = (int)v.x & (NE - 1); e1 = (int)v.y & (NE - 1);
        } else {
            e0 = v32.x & (NE - 1); e1 = v32.y & (NE - 1);
        }
    }

    if (!overflow) {
        if (valid) {
            ((float2*)out_w)[tok] = wv;
            if (idx_mode == 1) {
                ((float2*)out_idx)[tok] = make_float2((float)e0, (float)e1);
            } else if (idx_mode == 2) {
                longlong2 iv; iv.x = e0; iv.y = e1;
                ((longlong2*)out_idx)[tok] = iv;
            }
            if (out_mask) out_mask[tok] = ((wv.x + wv.y) == 0.0f) ? 1.0f : 0.0f;
        }
    } else {
        {
            const int e = t & (NE - 1), c = t >> 6;
            const int limA = b, limB = nbt + b;
            int accA = 0, accB = 0;
            for (int r = c; r < limB; r += 16) {
                int v = g_cnt[r][e];
                accB += v;
                if (r < limA) accA += v;
            }
            partA[c][e] = accA;
            partB[c][e] = accB;
        }
        ((int*)hA)[t] = 0; ((int*)hA)[t + TPB] = 0;
        ((int*)hB)[t] = 0; ((int*)hB)[t + TPB] = 0;
        if (t < 32 * NEP - 2 * TPB) { ((int*)hA)[t + 2 * TPB] = 0; ((int*)hB)[t + 2 * TPB] = 0; }
        __syncthreads();

        unsigned m0 = __match_any_sync(0xFFFFFFFFu, e0);
        unsigned m1 = __match_any_sync(0xFFFFFFFFu, e1);
        const int wr0 = __popc(m0 & lt), wr1 = __popc(m1 & lt);
        if (valid && wr0 == 0) hA[warp][e0] = __popc(m0);
        if (valid && wr1 == 0) hB[warp][e1] = __popc(m1);
        __syncthreads();

        #pragma unroll
        for (int k = 0; k < 4; k++) {
            const int p = warp * 4 + k;
            const int e = p & (NE - 1);
            const bool isB = p >= NE;
            int v = isB ? hB[lane][e] : hA[lane][e];
            int x = v;
            #pragma unroll
            for (int d = 1; d < 32; d <<= 1) {
                int y = __shfl_up_sync(0xFFFFFFFFu, x, d);
                if (lane >= d) x += y;
            }
            if (isB) hB[lane][e] = x - v; else hA[lane][e] = x - v;
            int pv = (lane < 16) ? (isB ? partB[lane][e] : partA[lane][e]) : 0;
            #pragma unroll
            for (int d = 8; d > 0; d >>= 1) pv += __shfl_xor_sync(0xFFFFFFFFu, pv, d);
            if (lane == 0) { if (isB) offB[e] = pv; else offA[e] = pv; }
        }
        __syncthreads();

        if (valid) {
            const int rank0 = offA[e0] + hA[warp][e0] + wr0;
            const int rank1 = offB[e1] + hB[warp][e1] + wr1;
            const float w0 = (rank0 < capacity) ? wv.x : 0.0f;
            const float w1 = (rank1 < capacity) ? wv.y : 0.0f;
            ((float2*)out_w)[tok] = make_float2(w0, w1);
            if (idx_mode == 1) {
                ((float2*)out_idx)[tok] = make_float2((float)e0, (float)e1);
            } else if (idx_mode == 2) {
                longlong2 iv; iv.x = e0; iv.y = e1;
                ((longlong2*)out_idx)[tok] = iv;
            }
            if (out_mask) out_mask[tok] = ((w0 + w1) == 0.0f) ? 1.0f : 0.0f;
        }
    }

    if (t == 0) {
        if (atomicAdd(&g_done2, 1) == (int)gridDim.x - 1) {
            #pragma unroll
            for (int e = 0; e < NE; e++) g_tot[e] = 0;
            g_done2 = 0;
        }
    }
}

extern "C" void kernel_launch(void* const* d_in, const int* in_sizes, int n_in,
                              void* d_out, int out_size) {
    const float* w    = (const float*)d_in[0];
    const void*  eidx = d_in[1];

    int flat  = in_sizes[0];                 // N * TOP_K
    int n_tok = flat / 2;
    int capacity = (flat * 5 + 255) / 256;   // ceil(1.25 * flat / 64)
    if (capacity < 1) capacity = 1;
    int nbt = (n_tok + EPT - 1) / EPT;
    if (2 * nbt > MAXROWS) nbt = MAXROWS / 2;   // guard (not hit at these sizes)

    float* out = (float*)d_out;
    float* out_w    = out;
    void*  out_idx  = nullptr;
    float* out_mask = nullptr;
    int idx_mode = 0;

    if (out_size >= 3 * flat + n_tok) {          // weights + i64 indices + mask
        idx_mode = 2; out_idx = out + flat; out_mask = out + 3 * flat;
    } else if (out_size >= 2 * flat + n_tok) {   // weights + 1-word indices + mask
        idx_mode = 1; out_idx = out + flat; out_mask = out + 2 * flat;
    } else if (out_size >= flat + n_tok) {       // weights + mask
        out_mask = out + flat;
    }

    if (nbt <= FUSE_MAX_BLOCKS) {
        k_fused<<<nbt, TPB>>>(w, eidx, n_tok, capacity, nbt,
                              out_w, out_idx, idx_mode, out_mask);
    } else {
        k_count<<<nbt, TPB>>>(eidx, n_tok, nbt);
        k_apply<<<nbt, TPB>>>(w, eidx, n_tok, capacity, nbt,
                              out_w, out_idx, idx_mode, out_mask);
    }
}

// round 14
// speedup vs baseline: 1.0208x; 1.0208x over previous
#include <cuda_runtime.h>
#include <cuda_bf16.h>
#include <cstdint>

// ExpertCapacityBuffer: N tokens, TOP_K=2, 64 experts.
// capacity = ceil(1.25*N*2/64). Flat slot-major: f = slot*N + tok.
// rank(f) = #{g<f : expert(g)==expert(f)}; keep iff rank < capacity.
//
// Overflow shortcut: expert e drops anything iff total(e) > capacity.
// Fused kernel with SPECULATIVE stores: outputs (assuming no overflow) are
// written during phase 1; after the counter barrier, blocks exit if no expert
// overflowed, else the exact-rank path overwrites all outputs.
// Fallback (big inputs): two-kernel pipeline.

#define NE   64
#define NEP  65              // padded row kills smem bank conflicts
#define TPB  1024
#define EPT  1024
#define MAXROWS 4096
#define FUSE_MAX_BLOCKS 132

__device__ int g_cnt[MAXROWS][NE];
__device__ int g_tot[NE];    // zero at start; reset by last block
__device__ int g_done  = 0;
__device__ int g_done2 = 0;

__device__ __forceinline__ int ld_acq(const int* p) {
    int v;
    asm volatile("ld.acquire.gpu.b32 %0, [%1];" : "=r"(v) : "l"(p) : "memory");
    return v;
}

// warp-0 dtype probe: int64 values <64 => odd 32-bit words of first 256B zero.
__device__ __forceinline__ void probe_w0(const void* eraw, int lane, int* s_is64) {
    if (threadIdx.x < 32) {
        unsigned x = ((const unsigned*)eraw)[2 * lane + 1];
        unsigned nz = __ballot_sync(0xFFFFFFFFu, x != 0u);
        if (lane == 0) *s_is64 = (nz == 0u);
    }
}
__device__ __forceinline__ bool probe_warp(const void* eraw) {
    unsigned x = ((const unsigned*)eraw)[2 * (threadIdx.x & 31) + 1];
    return __ballot_sync(0xFFFFFFFFu, x != 0u) == 0u;
}

// ================== FUSED kernel (co-resident grid) ==================
__global__ void __launch_bounds__(TPB, 1)
k_fused(const float* __restrict__ w, const void* __restrict__ eraw,
        int n_tok, int capacity, int nbt,
        float* __restrict__ out_w, void* __restrict__ out_idx, int idx_mode,
        float* __restrict__ out_mask) {
    __shared__ int hA[32][NEP];
    __shared__ int hB[32][NEP];
    __shared__ int partA[16][NE];
    __shared__ int partB[16][NE];
    __shared__ int offA[NE], offB[NE];
    __shared__ int s_is64;
    const int t = threadIdx.x, b = blockIdx.x;
    const int warp = t >> 5, lane = t & 31;
    const unsigned lt = (1u << lane) - 1u;

    const int tok = b * EPT + t;
    const bool valid = tok < n_tok;

    // ---- eager loads ----
    int2 v32 = make_int2(0, 0);
    float2 wv = make_float2(0.f, 0.f);
    if (valid) {
        v32 = __ldg((const int2*)eraw + tok);
        wv  = __ldg((const float2*)w + tok);
    }
    ((int*)hA)[t] = 0; ((int*)hA)[t + TPB] = 0;
    ((int*)hB)[t] = 0; ((int*)hB)[t + TPB] = 0;
    if (t < 32 * NEP - 2 * TPB) { ((int*)hA)[t + 2 * TPB] = 0; ((int*)hB)[t + 2 * TPB] = 0; }
    probe_w0(eraw, lane, &s_is64);
    __syncthreads();

    int e0 = NE + lane, e1 = NE + lane;      // unique keys for invalid lanes
    if (valid) {
        if (s_is64) {
            longlong2 v = __ldg((const longlong2*)eraw + tok);
            e0 = (int)v.x & (NE - 1); e1 = (int)v.y & (NE - 1);
        } else {
            e0 = v32.x & (NE - 1); e1 = v32.y & (NE - 1);
        }
    }

    // ---- SPECULATIVE final stores (correct iff no overflow) ----
    // Fire-and-forget; they drain while the histogram below proceeds.
    if (valid) {
        ((float2*)out_w)[tok] = wv;
        if (idx_mode == 1) {
            ((float2*)out_idx)[tok] = make_float2((float)e0, (float)e1);
        } else if (idx_mode == 2) {
            longlong2 iv; iv.x = e0; iv.y = e1;
            ((longlong2*)out_idx)[tok] = iv;
        }
        if (out_mask) out_mask[tok] = ((wv.x + wv.y) == 0.0f) ? 1.0f : 0.0f;
    }

    // ---- histogram ----
    unsigned m0 = __match_any_sync(0xFFFFFFFFu, e0);
    unsigned m1 = __match_any_sync(0xFFFFFFFFu, e1);
    const int wr0 = __popc(m0 & lt), wr1 = __popc(m1 & lt);
    if (valid && wr0 == 0) hA[warp][e0] = __popc(m0);
    if (valid && wr1 == 0) hB[warp][e1] = __popc(m1);
    __syncthreads();

    if (t < NE) {
        int s = 0;
        #pragma unroll
        for (int ww = 0; ww < 32; ww++) s += hA[ww][t];
        g_cnt[b][t] = s;
        if (s) atomicAdd(&g_tot[t], s);
    } else if (t < 2 * NE) {
        const int e = t - NE;
        int s = 0;
        #pragma unroll
        for (int ww = 0; ww < 32; ww++) s += hB[ww][e];
        g_cnt[nbt + b][e] = s;
        if (s) atomicAdd(&g_tot[e], s);
    }
    __syncthreads();

    // ---- single counter barrier ----
    if (t == 0) {
        __threadfence();
        atomicAdd(&g_done, 1);
        while (ld_acq(&g_done) < nbt) { }
    }
    __syncthreads();

    // ---- overflow check; fast case exits (outputs already written) ----
    const int ta = g_tot[lane], tb = g_tot[lane + 32];
    const bool overflow =
        __ballot_sync(0xFFFFFFFFu, (ta > capacity) || (tb > capacity)) != 0u;

    if (overflow) {
        // exact ranks; warp hists (hA/hB) and match regs still live
        {
            const int e = t & (NE - 1), c = t >> 6;
            const int limA = b, limB = nbt + b;
            int accA = 0, accB = 0;
            for (int r = c; r < limB; r += 16) {
                int v = g_cnt[r][e];
                accB += v;
                if (r < limA) accA += v;
            }
            partA[c][e] = accA;
            partB[c][e] = accB;
        }
        __syncthreads();

        #pragma unroll
        for (int k = 0; k < 4; k++) {
            const int p = warp * 4 + k;
            const int e = p & (NE - 1);
            const bool isB = p >= NE;
            int v = isB ? hB[lane][e] : hA[lane][e];
            int x = v;
            #pragma unroll
            for (int d = 1; d < 32; d <<= 1) {
                int y = __shfl_up_sync(0xFFFFFFFFu, x, d);
                if (lane >= d) x += y;
            }
            if (isB) hB[lane][e] = x - v; else hA[lane][e] = x - v;
            int pv = (lane < 16) ? (isB ? partB[lane][e] : partA[lane][e]) : 0;
            #pragma unroll
            for (int d = 8; d > 0; d >>= 1) pv += __shfl_xor_sync(0xFFFFFFFFu, pv, d);
            if (lane == 0) { if (isB) offB[e] = pv; else offA[e] = pv; }
        }
        __syncthreads();

        if (valid) {
            const int rank0 = offA[e0] + hA[warp][e0] + wr0;
            const int rank1 = offB[e1] + hB[warp][e1] + wr1;
            const float w0 = (rank0 < capacity) ? wv.x : 0.0f;
            const float w1 = (rank1 < capacity) ? wv.y : 0.0f;
            ((float2*)out_w)[tok] = make_float2(w0, w1);
            if (out_mask) out_mask[tok] = ((w0 + w1) == 0.0f) ? 1.0f : 0.0f;
        }
    }

    // ---- reset for next graph replay (last block; all g_tot reads done) ----
    if (t == 0) {
        if (atomicAdd(&g_done2, 1) == nbt - 1) {
            #pragma unroll
            for (int e = 0; e < NE; e++) g_tot[e] = 0;
            g_done = 0; g_done2 = 0;
        }
    }
}

// ================== Fallback two-kernel pipeline (large inputs) ==================
__global__ void __launch_bounds__(TPB)
k_count(const void* __restrict__ eraw, int n_tok, int nbt) {
    __shared__ int hA[32][NEP];
    __shared__ int hB[32][NEP];
    __shared__ int s_is64;
    const int t = threadIdx.x, b = blockIdx.x;
    const int warp = t >> 5, lane = t & 31;
    const unsigned lt = (1u << lane) - 1u;
    const int tok = b * EPT + t;
    const bool valid = tok < n_tok;

    int2 v32 = make_int2(0, 0);
    if (valid) v32 = __ldg((const int2*)eraw + tok);
    ((int*)hA)[t] = 0; ((int*)hA)[t + TPB] = 0;
    ((int*)hB)[t] = 0; ((int*)hB)[t + TPB] = 0;
    if (t < 32 * NEP - 2 * TPB) { ((int*)hA)[t + 2 * TPB] = 0; ((int*)hB)[t + 2 * TPB] = 0; }
    probe_w0(eraw, lane, &s_is64);
    __syncthreads();

    int e0 = NE + lane, e1 = NE + lane;
    if (valid) {
        if (s_is64) {
            longlong2 v = __ldg((const longlong2*)eraw + tok);
            e0 = (int)v.x & (NE - 1); e1 = (int)v.y & (NE - 1);
        } else {
            e0 = v32.x & (NE - 1); e1 = v32.y & (NE - 1);
        }
    }
    unsigned m0 = __match_any_sync(0xFFFFFFFFu, e0);
    unsigned m1 = __match_any_sync(0xFFFFFFFFu, e1);
    if (valid && !(m0 & lt)) hA[warp][e0] = __popc(m0);
    if (valid && !(m1 & lt)) hB[warp][e1] = __popc(m1);
    __syncthreads();

    if (t < NE) {
        int s = 0;
        #pragma unroll
        for (int ww = 0; ww < 32; ww++) s += hA[ww][t];
        g_cnt[b][t] = s;
        if (s) atomicAdd(&g_tot[t], s);
    } else if (t < 2 * NE) {
        const int e = t - NE;
        int s = 0;
        #pragma unroll
        for (int ww = 0; ww < 32; ww++) s += hB[ww][e];
        g_cnt[nbt + b][e] = s;
        if (s) atomicAdd(&g_tot[e], s);
    }
}

__global__ void __launch_bounds__(TPB)
k_apply(const float* __restrict__ w, const void* __restrict__ eraw,
        int n_tok, int capacity, int nbt,
        float* __restrict__ out_w, void* __restrict__ out_idx, int idx_mode,
        float* __restrict__ out_mask) {
    __shared__ int hA[32][NEP];
    __shared__ int hB[32][NEP];
    __shared__ int partA[16][NE];
    __shared__ int partB[16][NE];
    __shared__ int offA[NE], offB[NE];
    const int t = threadIdx.x, b = blockIdx.x;
    const int warp = t >> 5, lane = t & 31;
    const unsigned lt = (1u << lane) - 1u;
    const int tok = b * EPT + t;
    const bool valid = tok < n_tok;

    int2 v32 = make_int2(0, 0);
    float2 wv = make_float2(0.f, 0.f);
    if (valid) {
        v32 = __ldg((const int2*)eraw + tok);
        wv  = __ldg((const float2*)w + tok);
    }
    const bool is64 = probe_warp(eraw);
    const int ta = g_tot[lane], tb = g_tot[lane + 32];
    const bool overflow =
        __ballot_sync(0xFFFFFFFFu, (ta > capacity) || (tb > capacity)) != 0u;

    int e0 = NE + lane, e1 = NE + lane;
    if (valid && (overflow || idx_mode)) {
        if (is64) {
            longlong2 v = __ldg((const longlong2*)eraw + tok);
            e0 = (int)v.x & (NE - 1); e1 = (int)v.y & (NE - 1);
        } else {
            e0 = v32.x & (NE - 1); e1 = v32.y & (NE - 1);
        }
    }

    if (!overflow) {
        if (valid) {
            ((float2*)out_w)[tok] = wv;
            if (idx_mode == 1) {
                ((float2*)out_idx)[tok] = make_float2((float)e0, (float)e1);
            } else if (idx_mode == 2) {
                longlong2 iv; iv.x = e0; iv.y = e1;
                ((longlong2*)out_idx)[tok] = iv;
            }
            if (out_mask) out_mask[tok] = ((wv.x + wv.y) == 0.0f) ? 1.0f : 0.0f;
        }
    } else {
        {
            const int e = t & (NE - 1), c = t >> 6;
            const int limA = b, limB = nbt + b;
            int accA = 0, accB = 0;
            for (int r = c; r < limB; r += 16) {
                int v = g_cnt[r][e];
                accB += v;
                if (r < limA) accA += v;
            }
            partA[c][e] = accA;
            partB[c][e] = accB;
        }
        ((int*)hA)[t] = 0; ((int*)hA)[t + TPB] = 0;
        ((int*)hB)[t] = 0; ((int*)hB)[t + TPB] = 0;
        if (t < 32 * NEP - 2 * TPB) { ((int*)hA)[t + 2 * TPB] = 0; ((int*)hB)[t + 2 * TPB] = 0; }
        __syncthreads();

        unsigned m0 = __match_any_sync(0xFFFFFFFFu, e0);
        unsigned m1 = __match_any_sync(0xFFFFFFFFu, e1);
        const int wr0 = __popc(m0 & lt), wr1 = __popc(m1 & lt);
        if (valid && wr0 == 0) hA[warp][e0] = __popc(m0);
        if (valid && wr1 == 0) hB[warp][e1] = __popc(m1);
        __syncthreads();

        #pragma unroll
        for (int k = 0; k < 4; k++) {
            const int p = warp * 4 + k;
            const int e = p & (NE - 1);
            const bool isB = p >= NE;
            int v = isB ? hB[lane][e] : hA[lane][e];
            int x = v;
            #pragma unroll
            for (int d = 1; d < 32; d <<= 1) {
                int y = __shfl_up_sync(0xFFFFFFFFu, x, d);
                if (lane >= d) x += y;
            }
            if (isB) hB[lane][e] = x - v; else hA[lane][e] = x - v;
            int pv = (lane < 16) ? (isB ? partB[lane][e] : partA[lane][e]) : 0;
            #pragma unroll
            for (int d = 8; d > 0; d >>= 1) pv += __shfl_xor_sync(0xFFFFFFFFu, pv, d);
            if (lane == 0) { if (isB) offB[e] = pv; else offA[e] = pv; }
        }
        __syncthreads();

        if (valid) {
            const int rank0 = offA[e0] + hA[warp][e0] + wr0;
            const int rank1 = offB[e1] + hB[warp][e1] + wr1;
            const float w0 = (rank0 < capacity) ? wv.x : 0.0f;
            const float w1 = (rank1 < capacity) ? wv.y : 0.0f;
            ((float2*)out_w)[tok] = make_float2(w0, w1);
            if (idx_mode == 1) {
                ((float2*)out_idx)[tok] = make_float2((float)e0, (float)e1);
            } else if (idx_mode == 2) {
                longlong2 iv; iv.x = e0; iv.y = e1;
                ((longlong2*)out_idx)[tok] = iv;
            }
            if (out_mask) out_mask[tok] = ((w0 + w1) == 0.0f) ? 1.0f : 0.0f;
        }
    }

    if (t == 0) {
        if (atomicAdd(&g_done2, 1) == (int)gridDim.x - 1) {
            #pragma unroll
            for (int e = 0; e < NE; e++) g_tot[e] = 0;
            g_done2 = 0;
        }
    }
}

extern "C" void kernel_launch(void* const* d_in, const int* in_sizes, int n_in,
                              void* d_out, int out_size) {
    const float* w    = (const float*)d_in[0];
    const void*  eidx = d_in[1];

    int flat  = in_sizes[0];                 // N * TOP_K
    int n_tok = flat / 2;
    int capacity = (flat * 5 + 255) / 256;   // ceil(1.25 * flat / 64)
    if (capacity < 1) capacity = 1;
    int nbt = (n_tok + EPT - 1) / EPT;
    if (2 * nbt > MAXROWS) nbt = MAXROWS / 2;   // guard (not hit at these sizes)

    float* out = (float*)d_out;
    float* out_w    = out;
    void*  out_idx  = nullptr;
    float* out_mask = nullptr;
    int idx_mode = 0;

    if (out_size >= 3 * flat + n_tok) {          // weights + i64 indices + mask
        idx_mode = 2; out_idx = out + flat; out_mask = out + 3 * flat;
    } else if (out_size >= 2 * flat + n_tok) {   // weights + 1-word indices + mask
        idx_mode = 1; out_idx = out + flat; out_mask = out + 2 * flat;
    } else if (out_size >= flat + n_tok) {       // weights + mask
        out_mask = out + flat;
    }

    if (nbt <= FUSE_MAX_BLOCKS) {
        k_fused<<<nbt, TPB>>>(w, eidx, n_tok, capacity, nbt,
                              out_w, out_idx, idx_mode, out_mask);
    } else {
        k_count<<<nbt, TPB>>>(eidx, n_tok, nbt);
        k_apply<<<nbt, TPB>>>(w, eidx, n_tok, capacity, nbt,
                              out_w, out_idx, idx_mode, out_mask);
    }
}